// round 9
// baseline (speedup 1.0000x reference)
#include <cuda_runtime.h>
#include <cuda_bf16.h>

// LengthRegulator: out[b,t,:] = x[b, searchsorted(cumsum(dur[b]), t, 'right'), :]
// (zeros for t >= total duration). Shapes fixed by the problem:
//   x: [16, 512, 512] f32, durations: [16, 512] i32, out: [16, 4096, 512] f32.
//
// Streaming stores (R7 win) + 8-frame-per-warp source-row dedup: with __stcs
// the kernel window carries all LTS traffic, so cutting x re-reads from
// 74 MiB to ~31 MiB (E[distinct tokens per 8 frames] ~1.9) attacks the
// now-binding LTS cap directly.

static constexpr int B  = 16;
static constexpr int S  = 512;
static constexpr int H  = 512;
static constexpr int T  = 4096;
static constexpr int H4 = H / 4;          // 128 float4 per row
static constexpr int FPW = 8;             // frames per warp

// Scratch: per-frame source-token index (S means "invalid / zero frame").
__device__ int g_idx[B * T];

// One block per batch. Warp-shuffle inclusive scan, then scatter: token j
// writes its index over frames [cum[j-1], cum[j]); tail gets S.
__global__ void scan_idx_kernel(const int* __restrict__ durations) {
    __shared__ int warp_sums[16];
    __shared__ int s_total;
    const int b    = blockIdx.x;
    const int tid  = threadIdx.x;         // blockDim.x == S == 512
    const int lane = tid & 31;
    const int wid  = tid >> 5;            // 16 warps

    const int d = durations[b * S + tid];

    int v = d;
    #pragma unroll
    for (int off = 1; off < 32; off <<= 1) {
        int n = __shfl_up_sync(0xffffffffu, v, off);
        if (lane >= off) v += n;
    }
    if (lane == 31) warp_sums[wid] = v;
    __syncthreads();

    if (wid == 0 && lane < 16) {
        int w = warp_sums[lane];
        #pragma unroll
        for (int off = 1; off < 16; off <<= 1) {
            int n = __shfl_up_sync(0xffffu, w, off);
            if (lane >= off) w += n;
        }
        warp_sums[lane] = w;
        if (lane == 15) s_total = w;
    }
    __syncthreads();

    const int cum   = v + (wid > 0 ? warp_sums[wid - 1] : 0);  // inclusive
    const int start = cum - d;                                  // exclusive
    const int total = s_total;
    int* __restrict__ gi = g_idx + b * T;

    for (int t = start; t < cum; ++t) gi[t] = tid;
    for (int t = total + tid; t < T; t += S) gi[t] = S;
}

// One WARP per 8 consecutive output frames. One LDG fetches all 8 indices
// (lane<8 + shuffle). The 2KB source row is reloaded into registers only when
// the (warp-uniform) index changes; every frame is stored with __stcs.
__global__ void gather_kernel(const float4* __restrict__ x,
                              float4* __restrict__ out) {
    const int w    = blockIdx.x * (blockDim.x >> 5) + (threadIdx.x >> 5);
    const int lane = threadIdx.x & 31;
    const int row0 = w * FPW;             // aligned: T % FPW == 0, same batch
    const int b    = row0 >> 12;          // / T

    // Fetch the 8 frame indices with a single coalesced LDG.
    const int myidx = (lane < FPW) ? g_idx[row0 + lane] : 0;

    const float4* xb = x + ((long long)(b << 9) << 7);
    const float4 z = make_float4(0.f, 0.f, 0.f, 0.f);
    float4 v0 = z, v1 = z, v2 = z, v3 = z;
    int cur = -1;

    float4* o = out + ((long long)row0 << 7);
    #pragma unroll 1
    for (int r = 0; r < FPW; ++r, o += H4) {
        const int idx = __shfl_sync(0xffffffffu, myidx, r);
        if (idx < S) {
            if (idx != cur) {             // reload only on token change (~1.9x)
                const float4* s = xb + ((long long)idx << 7);
                v0 = s[lane];      v1 = s[lane + 32];
                v2 = s[lane + 64]; v3 = s[lane + 96];
                cur = idx;
            }
            __stcs(&o[lane],      v0);  __stcs(&o[lane + 32], v1);
            __stcs(&o[lane + 64], v2);  __stcs(&o[lane + 96], v3);
        } else {
            __stcs(&o[lane],      z);   __stcs(&o[lane + 32], z);
            __stcs(&o[lane + 64], z);   __stcs(&o[lane + 96], z);
        }
    }
}

extern "C" void kernel_launch(void* const* d_in, const int* in_sizes, int n_in,
                              void* d_out, int out_size) {
    const float* x   = (const float*)d_in[0];      // [B, S, H] f32
    const int*   dur = (const int*)d_in[1];        // [B, S]   i32
    float*       out = (float*)d_out;              // [B, T, H] f32
    (void)in_sizes; (void)n_in; (void)out_size;

    scan_idx_kernel<<<B, S>>>(dur);

    const int threads = 256;                       // 8 warps/block
    const int warps   = (B * T) / FPW;             // 8192
    const int blocks  = warps / (threads / 32);    // 1024
    gather_kernel<<<blocks, threads>>>((const float4*)x, (float4*)out);
}

// round 10
// speedup vs baseline: 1.1242x; 1.1242x over previous
#include <cuda_runtime.h>
#include <cuda_bf16.h>

// LengthRegulator: out[b,t,:] = x[b, searchsorted(cumsum(dur[b]), t, 'right'), :]
// (zeros for t >= total duration). Shapes fixed by the problem:
//   x: [16, 512, 512] f32, durations: [16, 512] i32, out: [16, 4096, 512] f32.
//
// R7's streaming-store structure (16384 short uniform warps -> smooth period)
// with 4-frame register dedup (reads ~47 MiB vs 74 MiB) — the FPW=4 midpoint
// between R7 (FPW=2, best period) and R9 (FPW=8, best kernel, worse period).

static constexpr int B  = 16;
static constexpr int S  = 512;
static constexpr int H  = 512;
static constexpr int T  = 4096;
static constexpr int H4 = H / 4;          // 128 float4 per row
static constexpr int FPW = 4;             // frames per warp

// Scratch: per-frame source-token index (S means "invalid / zero frame").
__device__ int g_idx[B * T];

// One block per batch. Warp-shuffle inclusive scan, then scatter: token j
// writes its index over frames [cum[j-1], cum[j]); tail gets S.
__global__ void scan_idx_kernel(const int* __restrict__ durations) {
    __shared__ int warp_sums[16];
    __shared__ int s_total;
    const int b    = blockIdx.x;
    const int tid  = threadIdx.x;         // blockDim.x == S == 512
    const int lane = tid & 31;
    const int wid  = tid >> 5;            // 16 warps

    const int d = durations[b * S + tid];

    int v = d;
    #pragma unroll
    for (int off = 1; off < 32; off <<= 1) {
        int n = __shfl_up_sync(0xffffffffu, v, off);
        if (lane >= off) v += n;
    }
    if (lane == 31) warp_sums[wid] = v;
    __syncthreads();

    if (wid == 0 && lane < 16) {
        int w = warp_sums[lane];
        #pragma unroll
        for (int off = 1; off < 16; off <<= 1) {
            int n = __shfl_up_sync(0xffffu, w, off);
            if (lane >= off) w += n;
        }
        warp_sums[lane] = w;
        if (lane == 15) s_total = w;
    }
    __syncthreads();

    const int cum   = v + (wid > 0 ? warp_sums[wid - 1] : 0);  // inclusive
    const int start = cum - d;                                  // exclusive
    const int total = s_total;
    int* __restrict__ gi = g_idx + b * T;

    for (int t = start; t < cum; ++t) gi[t] = tid;
    for (int t = total + tid; t < T; t += S) gi[t] = S;
}

// One WARP per 4 consecutive output frames, fully unrolled. Indices fetched
// with one coalesced LDG (lane<4) + shuffles. The 2KB source row is reloaded
// into registers only when the warp-uniform index changes (~1.46x per warp).
// All output stores are streaming (evict-first).
__global__ void gather_kernel(const float4* __restrict__ x,
                              float4* __restrict__ out) {
    const int w    = blockIdx.x * (blockDim.x >> 5) + (threadIdx.x >> 5);
    const int lane = threadIdx.x & 31;
    const int row0 = w * FPW;             // aligned; all 4 frames same batch
    const int b    = row0 >> 12;          // / T

    const int myidx = (lane < FPW) ? g_idx[row0 + lane] : 0;

    const float4* xb = x + ((long long)(b << 9) << 7);
    const float4 z = make_float4(0.f, 0.f, 0.f, 0.f);
    float4 v0 = z, v1 = z, v2 = z, v3 = z;
    int cur = -1;

    float4* o = out + ((long long)row0 << 7);
    #pragma unroll
    for (int r = 0; r < FPW; ++r, o += H4) {
        const int idx = __shfl_sync(0xffffffffu, myidx, r);
        if (idx < S) {
            if (idx != cur) {             // reload only on token change
                const float4* s = xb + ((long long)idx << 7);
                v0 = s[lane];      v1 = s[lane + 32];
                v2 = s[lane + 64]; v3 = s[lane + 96];
                cur = idx;
            }
            __stcs(&o[lane],      v0);  __stcs(&o[lane + 32], v1);
            __stcs(&o[lane + 64], v2);  __stcs(&o[lane + 96], v3);
        } else {
            __stcs(&o[lane],      z);   __stcs(&o[lane + 32], z);
            __stcs(&o[lane + 64], z);   __stcs(&o[lane + 96], z);
        }
    }
}

extern "C" void kernel_launch(void* const* d_in, const int* in_sizes, int n_in,
                              void* d_out, int out_size) {
    const float* x   = (const float*)d_in[0];      // [B, S, H] f32
    const int*   dur = (const int*)d_in[1];        // [B, S]   i32
    float*       out = (float*)d_out;              // [B, T, H] f32
    (void)in_sizes; (void)n_in; (void)out_size;

    scan_idx_kernel<<<B, S>>>(dur);

    const int threads = 256;                       // 8 warps/block
    const int warps   = (B * T) / FPW;             // 16384
    const int blocks  = warps / (threads / 32);    // 2048
    gather_kernel<<<blocks, threads>>>((const float4*)x, (float4*)out);
}

// round 11
// speedup vs baseline: 1.1914x; 1.0598x over previous
#include <cuda_runtime.h>
#include <cuda_bf16.h>

// LengthRegulator: out[b,t,:] = x[b, searchsorted(cumsum(dur[b]), t, 'right'), :]
// (zeros for t >= total duration). Shapes fixed by the problem:
//   x: [16, 512, 512] f32, durations: [16, 512] i32, out: [16, 4096, 512] f32.
//
// Period law measured across FPW=2/4/8: in-kernel time ~flat, but the
// end-of-kernel streaming-store drain tail scales with per-warp work.
// Endpoint: FPW=1 (one warp per output row, shortest uniform warps) +
// 128-thread blocks (1 warp/SMSP) + __stcs evict-first stores.

static constexpr int B  = 16;
static constexpr int S  = 512;
static constexpr int H  = 512;
static constexpr int T  = 4096;
static constexpr int H4 = H / 4;          // 128 float4 per row

// Scratch: per-frame source-token index (S means "invalid / zero frame").
__device__ int g_idx[B * T];

// One block per batch. Warp-shuffle inclusive scan, then scatter: token j
// writes its index over frames [cum[j-1], cum[j]); tail gets S.
__global__ void scan_idx_kernel(const int* __restrict__ durations) {
    __shared__ int warp_sums[16];
    __shared__ int s_total;
    const int b    = blockIdx.x;
    const int tid  = threadIdx.x;         // blockDim.x == S == 512
    const int lane = tid & 31;
    const int wid  = tid >> 5;            // 16 warps

    const int d = durations[b * S + tid];

    int v = d;
    #pragma unroll
    for (int off = 1; off < 32; off <<= 1) {
        int n = __shfl_up_sync(0xffffffffu, v, off);
        if (lane >= off) v += n;
    }
    if (lane == 31) warp_sums[wid] = v;
    __syncthreads();

    if (wid == 0 && lane < 16) {
        int w = warp_sums[lane];
        #pragma unroll
        for (int off = 1; off < 16; off <<= 1) {
            int n = __shfl_up_sync(0xffffu, w, off);
            if (lane >= off) w += n;
        }
        warp_sums[lane] = w;
        if (lane == 15) s_total = w;
    }
    __syncthreads();

    const int cum   = v + (wid > 0 ? warp_sums[wid - 1] : 0);  // inclusive
    const int start = cum - d;                                  // exclusive
    const int total = s_total;
    int* __restrict__ gi = g_idx + b * T;

    for (int t = start; t < cum; ++t) gi[t] = tid;
    for (int t = total + tid; t < T; t += S) gi[t] = S;
}

// One WARP per output row: 4 independent LDG.128 + 8 streaming STG.128 per
// lane-group, perfectly uniform, shortest possible warp lifetime.
__global__ void __launch_bounds__(128)
gather_kernel(const float4* __restrict__ x, float4* __restrict__ out) {
    const int row  = blockIdx.x * (blockDim.x >> 5) + (threadIdx.x >> 5);
    const int lane = threadIdx.x & 31;
    const int b    = row >> 12;           // / T

    const int idx = g_idx[row];           // warp-uniform (1 sector)
    float4* o = out + ((long long)row << 7);

    if (idx < S) {
        const float4* s = x + ((long long)((b << 9) + idx) << 7);
        float4 v0 = s[lane];
        float4 v1 = s[lane + 32];
        float4 v2 = s[lane + 64];
        float4 v3 = s[lane + 96];
        __stcs(&o[lane],      v0);
        __stcs(&o[lane + 32], v1);
        __stcs(&o[lane + 64], v2);
        __stcs(&o[lane + 96], v3);
    } else {
        const float4 z = make_float4(0.f, 0.f, 0.f, 0.f);
        __stcs(&o[lane],      z);
        __stcs(&o[lane + 32], z);
        __stcs(&o[lane + 64], z);
        __stcs(&o[lane + 96], z);
    }
}

extern "C" void kernel_launch(void* const* d_in, const int* in_sizes, int n_in,
                              void* d_out, int out_size) {
    const float* x   = (const float*)d_in[0];      // [B, S, H] f32
    const int*   dur = (const int*)d_in[1];        // [B, S]   i32
    float*       out = (float*)d_out;              // [B, T, H] f32
    (void)in_sizes; (void)n_in; (void)out_size;

    scan_idx_kernel<<<B, S>>>(dur);

    const int threads = 128;                       // 4 warps = 4 rows/block
    const int blocks  = (B * T) / (threads / 32);  // 16384
    gather_kernel<<<blocks, threads>>>((const float4*)x, (float4*)out);
}